// round 16
// baseline (speedup 1.0000x reference)
#include <cuda_runtime.h>
#include <cstdint>

// out[i] = sum_j relu(adj[i,j] * Linv[i,j]) * W[j] + b
// N = 8192. Inputs: d_in[0]=x_e (unused), d_in[1]=Linv, d_in[2]=adjacency,
// d_in[3]=W (N floats), d_in[4]=b (1 float). Output: N floats ([N,1]).
//
// Single kernel, one row per 128-thread CTA (grid 8192, 16 CTAs/SM -> fine
// scheduling granularity, no combine). Stream loads use ld.global.cs with an
// L2::256B prefetch hint to improve DRAM-side queueing on the two sequential
// streams. W via __ldg (L2/L1-resident), bias added once per row.

#define N_DIM 8192
#define THREADS 128
#define F4_PER_ROW (N_DIM / 4)   // 2048 -> 16 iters per thread

__device__ __forceinline__ float4 ldcs_pf256(const float4* p) {
    float4 v;
    asm volatile("ld.global.cs.L2::256B.v4.f32 {%0,%1,%2,%3}, [%4];"
                 : "=f"(v.x), "=f"(v.y), "=f"(v.z), "=f"(v.w)
                 : "l"(p));
    return v;
}

__global__ __launch_bounds__(THREADS, 16)
void dist2cycle_row128_kernel(const float4* __restrict__ Linv,
                              const float4* __restrict__ adj,
                              const float4* __restrict__ W4,
                              const float*  __restrict__ bptr,
                              float* __restrict__ out) {
    const int row = blockIdx.x;
    const size_t base = (size_t)row * F4_PER_ROW;
    const float4* __restrict__ L = Linv + base;
    const float4* __restrict__ A = adj  + base;

    float acc = 0.0f;

    // 2048 float4 over 128 threads -> 16 iterations.
    #pragma unroll 8
    for (int j = threadIdx.x; j < F4_PER_ROW; j += THREADS) {
        float4 l = ldcs_pf256(&L[j]);
        float4 a = ldcs_pf256(&A[j]);
        float4 w = __ldg(&W4[j]);
        acc = fmaf(fmaxf(a.x * l.x, 0.0f), w.x, acc);
        acc = fmaf(fmaxf(a.y * l.y, 0.0f), w.y, acc);
        acc = fmaf(fmaxf(a.z * l.z, 0.0f), w.z, acc);
        acc = fmaf(fmaxf(a.w * l.w, 0.0f), w.w, acc);
    }

    // Warp reduce
    #pragma unroll
    for (int off = 16; off > 0; off >>= 1)
        acc += __shfl_xor_sync(0xFFFFFFFFu, acc, off);

    // Block reduce across 4 warps
    __shared__ float warp_sums[THREADS / 32];
    const int lane = threadIdx.x & 31;
    const int wid  = threadIdx.x >> 5;
    if (lane == 0) warp_sums[wid] = acc;
    __syncthreads();

    if (wid == 0) {
        float v = (lane < THREADS / 32) ? warp_sums[lane] : 0.0f;
        #pragma unroll
        for (int off = 2; off > 0; off >>= 1)
            v += __shfl_xor_sync(0xFFFFFFFFu, v, off);
        if (lane == 0)
            out[row] = v + __ldg(bptr);
    }
}

extern "C" void kernel_launch(void* const* d_in, const int* in_sizes, int n_in,
                              void* d_out, int out_size) {
    // metadata order: x_e, Linv, adjacency, W, b
    const float4* Linv = (const float4*)d_in[1];
    const float4* adj  = (const float4*)d_in[2];
    const float4* W4   = (const float4*)d_in[3];
    const float*  b    = (const float*)d_in[4];
    float* out = (float*)d_out;

    dist2cycle_row128_kernel<<<N_DIM, THREADS>>>(Linv, adj, W4, b, out);
}

// round 17
// speedup vs baseline: 1.1483x; 1.1483x over previous
#include <cuda_runtime.h>

// out[i] = sum_j relu(adj[i,j] * Linv[i,j]) * W[j] + b
// N = 8192. Inputs: d_in[0]=x_e (unused), d_in[1]=Linv, d_in[2]=adjacency,
// d_in[3]=W (N floats), d_in[4]=b (1 float). Output: N floats ([N,1]).
//
// FINAL: single launch, 16384 CTAs, one per HALF-row (best-measured wave
// packing). Each CTA streams its 32KB half via LDG.128 (.cs on the two big
// streams, .ca on L2-resident W), reduces, and the second CTA per row
// combines both halves + bias via the last-block threadfence pattern,
// resetting the flag for clean graph replays. Deterministic: combine is
// always p0 + p1 + b. Measured 78.18us, DRAM 85%, ~6.76 TB/s — at the
// practical HBM roofline for this 512MB compulsory-read workload.

#define N_DIM 8192
#define THREADS 256
#define HALF_F4 (N_DIM / 4 / 2)   // 1024 float4 per half-row

__device__ float g_partials[2 * N_DIM];
__device__ int   g_flags[N_DIM];          // zero-init at load; reset after use

__global__ __launch_bounds__(THREADS, 8)
void dist2cycle_halfrow_fused_kernel(const float4* __restrict__ Linv,
                                     const float4* __restrict__ adj,
                                     const float4* __restrict__ W4,
                                     const float*  __restrict__ bptr,
                                     float* __restrict__ out) {
    const int row  = blockIdx.x >> 1;
    const int half = blockIdx.x & 1;

    const size_t base = (size_t)row * (N_DIM / 4) + (size_t)half * HALF_F4;
    const float4* __restrict__ L = Linv + base;
    const float4* __restrict__ A = adj  + base;
    const float4* __restrict__ W = W4 + (size_t)half * HALF_F4;

    float acc = 0.0f;

    // 1024 float4 over 256 threads -> 4 iterations.
    #pragma unroll 4
    for (int j = threadIdx.x; j < HALF_F4; j += THREADS) {
        float4 l = __ldcs(&L[j]);
        float4 a = __ldcs(&A[j]);
        float4 w = __ldg(&W[j]);
        acc = fmaf(fmaxf(a.x * l.x, 0.0f), w.x, acc);
        acc = fmaf(fmaxf(a.y * l.y, 0.0f), w.y, acc);
        acc = fmaf(fmaxf(a.z * l.z, 0.0f), w.z, acc);
        acc = fmaf(fmaxf(a.w * l.w, 0.0f), w.w, acc);
    }

    // Warp reduce
    #pragma unroll
    for (int off = 16; off > 0; off >>= 1)
        acc += __shfl_xor_sync(0xFFFFFFFFu, acc, off);

    // Block reduce across 8 warps
    __shared__ float warp_sums[THREADS / 32];
    const int lane = threadIdx.x & 31;
    const int wid  = threadIdx.x >> 5;
    if (lane == 0) warp_sums[wid] = acc;
    __syncthreads();

    if (wid == 0) {
        float v = (lane < THREADS / 32) ? warp_sums[lane] : 0.0f;
        #pragma unroll
        for (int off = 4; off > 0; off >>= 1)
            v += __shfl_xor_sync(0xFFFFFFFFu, v, off);

        if (lane == 0) {
            // Publish this half's partial, then decide who combines.
            g_partials[2 * row + half] = v;
            __threadfence();
            int prev = atomicAdd(&g_flags[row], 1);
            if (prev == 1) {
                // Second arriver: peer's partial is visible (it fenced
                // before its atomic; atomics on g_flags[row] serialize).
                volatile float* gp = g_partials;
                float p0 = gp[2 * row + 0];
                float p1 = gp[2 * row + 1];
                out[row] = p0 + p1 + __ldg(bptr);
                g_flags[row] = 0;   // reset for next graph replay
            }
        }
    }
}

extern "C" void kernel_launch(void* const* d_in, const int* in_sizes, int n_in,
                              void* d_out, int out_size) {
    // metadata order: x_e, Linv, adjacency, W, b
    const float4* Linv = (const float4*)d_in[1];
    const float4* adj  = (const float4*)d_in[2];
    const float4* W4   = (const float4*)d_in[3];
    const float*  b    = (const float*)d_in[4];
    float* out = (float*)d_out;

    dist2cycle_halfrow_fused_kernel<<<2 * N_DIM, THREADS>>>(Linv, adj, W4, b, out);
}